// round 13
// baseline (speedup 1.0000x reference)
#include <cuda_runtime.h>

namespace {
constexpr int kB    = 64;
constexpr int kNH   = 16;
constexpr int kNKV  = 2;
constexpr int kHD   = 128;
constexpr int kMax  = 8192;
constexpr int kHid  = 2048;
constexpr int kStart= 8191;
constexpr int kSplit= 23;
constexpr int kChunk= 357;   // 23*357 = 8211 >= 8191
constexpr int kNS   = 7;     // attn cp.async ring stages per warp (deepened)
// GEMM smem: xs half-K 8x1024 floats (32KB) + weight ring 8 warps x 4 stages x 2KB (64KB)
constexpr int kGemmSmem = 32 * 1024 + 64 * 1024;
}

typedef unsigned long long u64;

__device__ __align__(16) float g_q[kB * kNH * kHD];     // pre-RoPE q
__device__ __align__(16) float g_k[kB * kNKV * kHD];    // pre-RoPE k
__device__ __align__(16) float g_v[kB * kNKV * kHD];
__device__ __align__(16) float g_attn[kB * kHid];
__device__ __align__(16) float g_pacc[kB * kNKV * kSplit * 8 * kHD];
__device__ __align__(16) float g_pl[kB * kNKV * kSplit * 8];
__device__ int g_cnt[kB * kNKV];                        // split-arrival counters

__device__ __forceinline__ u64 pack2(float lo, float hi) {
    u64 r; asm("mov.b64 %0,{%1,%2};" : "=l"(r) : "f"(lo), "f"(hi)); return r;
}
__device__ __forceinline__ void unpack2(u64 v, float& lo, float& hi) {
    asm("mov.b64 {%0,%1},%2;" : "=f"(lo), "=f"(hi) : "l"(v));
}
__device__ __forceinline__ void fma2(u64& d, u64 a, u64 b) {
    asm("fma.rn.f32x2 %0,%1,%2,%0;" : "+l"(d) : "l"(a), "l"(b));
}
__device__ __forceinline__ u64 mul2(u64 a, u64 b) {
    u64 r; asm("mul.rn.f32x2 %0,%1,%2;" : "=l"(r) : "l"(a), "l"(b)); return r;
}
__device__ __forceinline__ u64 add2(u64 a, u64 b) {
    u64 r; asm("add.rn.f32x2 %0,%1,%2;" : "=l"(r) : "l"(a), "l"(b)); return r;
}
__device__ __forceinline__ u64 shfl64x(u64 v, int m) {
    return __shfl_xor_sync(0xffffffffu, v, m);
}
__device__ __forceinline__ void cpasync16(unsigned saddr, const void* g) {
    asm volatile("cp.async.cg.shared.global [%0], [%1], 16;" :: "r"(saddr), "l"(g));
}
__device__ __forceinline__ void cpcommit() {
    asm volatile("cp.async.commit_group;" ::: "memory");
}
template <int N>
__device__ __forceinline__ void cpwaitg() {
    asm volatile("cp.async.wait_group %0;" :: "n"(N) : "memory");
}

// ---------------------------------------------------------------------------
// GEMM: out[b][o] = sum_k X[b][k] * W[o][k] + bias[o];  K fixed = 2048.
// block = 256 (8 warps). CTA tile: 32 outputs x 8 batches; warp: 4 outputs.
// K processed in 2 halves of 1024. X half staged in 32KB smem; weights stream
// through a warp-private 4-stage cp.async ring (lookahead = 4 iterations).
// Stage-reuse fill is issued AFTER the wv LDS of the stage being reused.
__device__ __forceinline__ void gemm_body(const float* __restrict__ X,
                                          const float* __restrict__ W,
                                          const float* __restrict__ bias,
                                          float* __restrict__ out,
                                          int N, int b0, int o0) {
    extern __shared__ float4 dynsm4[];
    float4* xs = dynsm4;                       // [8][256] float4 (one K-half)
    float4* ws = dynsm4 + 2048;                // [8 warps][4 stages][128] float4
    const unsigned xs_s = (unsigned)__cvta_generic_to_shared(xs);
    const unsigned ws_s = (unsigned)__cvta_generic_to_shared(ws);

    const int tid  = threadIdx.x;
    const int w    = tid >> 5;
    const int lane = tid & 31;
    const int ob   = o0 + w * 4;
    const int hb   = lane >> 2;

    const unsigned wbase = ws_s + (unsigned)(w * 4) * 128 * 16;

    u64 acc[8][4];
#pragma unroll
    for (int i = 0; i < 8; i++)
#pragma unroll
        for (int j = 0; j < 4; j++) acc[i][j] = 0ull;

#pragma unroll 1
    for (int kc = 0; kc < 2; kc++) {
        __syncthreads();                       // prior half's xs reads retired
        // X half: 2048 16B chunks, 8 per thread.
#pragma unroll
        for (int j = 0; j < 8; j++) {
            int c = tid + j * 256;             // c>>8 = batch, c&255 = float4 idx
            cpasync16(xs_s + c * 16,
                      X + (size_t)(b0 + (c >> 8)) * kHid + kc * 1024 + (c & 255) * 4);
        }
        cpcommit();                            // commit: X

        auto fill_w = [&](int ki, int s) {     // stage = 4 rows x 32 float4 (2KB)
#pragma unroll
            for (int j = 0; j < 4; j++) {
                int c = lane + j * 32;         // row = c>>5, f4 = c&31
                cpasync16(wbase + (unsigned)(s * 128 + c) * 16,
                          W + (size_t)(ob + (c >> 5)) * kHid + kc * 1024 +
                              ki * 128 + (c & 31) * 4);
            }
        };
#pragma unroll
        for (int s = 0; s < 4; s++) { fill_w(s, s); cpcommit(); }  // W0..W3

        cpwaitg<3>();                          // X + W0 complete
        __syncthreads();                       // xs visible CTA-wide

#pragma unroll 1
        for (int ki = 0; ki < 8; ki++) {
            cpwaitg<3>();                      // stage ki complete (warp FIFO)

            const float4* wrow = ws + (w * 4 + (ki & 3)) * 128;
            ulonglong2 wv[4];
#pragma unroll
            for (int oo = 0; oo < 4; oo++)
                wv[oo] = *reinterpret_cast<const ulonglong2*>(wrow + oo * 32 + lane);

            if (ki + 4 < 8) fill_w(ki + 4, ki & 3);   // reuse after LDS
            cpcommit();                        // one commit per iter (may be empty)

            const int kk = ki * 32 + lane;
#pragma unroll
            for (int ih = 0; ih < 8; ih++) {
                ulonglong2 xv = *reinterpret_cast<const ulonglong2*>(
                    xs + ((hb ^ ih) << 8) + kk);
#pragma unroll
                for (int oo = 0; oo < 4; oo++) {
                    fma2(acc[ih][oo], xv.x, wv[oo].x);
                    fma2(acc[ih][oo], xv.y, wv[oo].y);
                }
            }
        }
    }

    // Epilogue: slot ih on lane l holds batch (l>>2)^ih. XOR-fold per oo.
    float s[4][8];
#pragma unroll
    for (int ih = 0; ih < 8; ih++)
#pragma unroll
        for (int oo = 0; oo < 4; oo++) {
            float lo, hi; unpack2(acc[ih][oo], lo, hi);
            s[oo][ih] = lo + hi;
        }
#pragma unroll
    for (int oo = 0; oo < 4; oo++) {
#pragma unroll
        for (int i = 0; i < 4; i++) s[oo][i] += __shfl_xor_sync(0xffffffffu, s[oo][i ^ 4], 16);
#pragma unroll
        for (int i = 0; i < 2; i++) s[oo][i] += __shfl_xor_sync(0xffffffffu, s[oo][i ^ 2], 8);
        s[oo][0] += __shfl_xor_sync(0xffffffffu, s[oo][1], 4);
        s[oo][0] += __shfl_xor_sync(0xffffffffu, s[oo][0], 2);
        s[oo][0] += __shfl_xor_sync(0xffffffffu, s[oo][0], 1);
    }
    float r01 = (lane & 1) ? s[1][0] : s[0][0];
    float r23 = (lane & 1) ? s[3][0] : s[2][0];
    float r   = (lane & 2) ? r23 : r01;
    int oo = lane & 3;
    float bv = bias ? bias[ob + oo] : 0.f;
    out[(size_t)(b0 + hb) * N + ob + oo] = r + bv;
}

// Fused QKV: blocks 0..63 -> q (N=2048), 64..71 -> k, 72..79 -> v (N=256).
// Block (0,0) also resets the split-arrival counters for attn's fused reduce.
__global__ void __launch_bounds__(256, 2)
qkv_kernel(const float* __restrict__ X,
           const float* __restrict__ wq, const float* __restrict__ bq,
           const float* __restrict__ wk, const float* __restrict__ bk,
           const float* __restrict__ wv, const float* __restrict__ bv) {
    const int bx = blockIdx.x;
    const int b0 = blockIdx.y * 8;
    if (bx == 0 && blockIdx.y == 0 && threadIdx.x < kB * kNKV)
        g_cnt[threadIdx.x] = 0;
    if (bx < 64)       gemm_body(X, wq, bq, g_q, kHid, b0, bx * 32);
    else if (bx < 72)  gemm_body(X, wk, bk, g_k, 256, b0, (bx - 64) * 32);
    else               gemm_body(X, wv, bv, g_v, 256, b0, (bx - 72) * 32);
}

__global__ void __launch_bounds__(256, 2)
out_gemm_kernel(const float* __restrict__ X, const float* __restrict__ W,
                float* __restrict__ out) {
    gemm_body(X, W, nullptr, out, kHid, blockIdx.y * 8, blockIdx.x * 32);
}

// ---------------------------------------------------------------------------
// One timestep, packed head-pair scores.
// Lane ell owns dims [4*ell, 4*ell+4); slot i <-> head (ell>>2)^i.
// qp[d][j] = (q_{slot 2j, dim d}, q_{slot 2j+1, dim d}), pre-scaled.
__device__ __forceinline__ void attn_step(const float4 kf, const float4 vf,
                                          const u64 (* __restrict__ qp)[4],
                                          float& l,
                                          u64* __restrict__ a0,
                                          u64* __restrict__ a1) {
    const u64 kd0 = pack2(kf.x, kf.x);
    const u64 kd1 = pack2(kf.y, kf.y);
    const u64 kd2 = pack2(kf.z, kf.z);
    const u64 kd3 = pack2(kf.w, kf.w);

    u64 p[4];
#pragma unroll
    for (int j = 0; j < 4; j++) {
        p[j] = mul2(kd0, qp[0][j]);
        fma2(p[j], kd1, qp[1][j]);
        fma2(p[j], kd2, qp[2][j]);
        fma2(p[j], kd3, qp[3][j]);
    }
    // Packed XOR fold: pair j holds slots (2j, 2j+1).
    p[0] = add2(p[0], shfl64x(p[2], 16));     // level 16: partner pair j^2
    p[1] = add2(p[1], shfl64x(p[3], 16));
    p[0] = add2(p[0], shfl64x(p[1], 8));      // level 8:  partner pair j^1
    u64 t = shfl64x(p[0], 4);                 // level 4:  cross within pair
    float s0, s1_, t0_, t1;
    unpack2(p[0], s0, s1_);
    unpack2(t, t0_, t1);
    float s = s0 + t1;
    s += __shfl_xor_sync(0xffffffffu, s, 2);
    s += __shfl_xor_sync(0xffffffffu, s, 1);

    float pe;                                  // q pre-scaled by scale*log2(e)
    asm("ex2.approx.f32 %0, %1;" : "=f"(pe) : "f"(s));
    l += pe;                                   // denominator of head lane>>2

    float g0 = pe;
    float g1 = __shfl_xor_sync(0xffffffffu, g0, 4);
    float g2 = __shfl_xor_sync(0xffffffffu, g0, 8);
    float g3 = __shfl_xor_sync(0xffffffffu, g1, 8);
    float g4 = __shfl_xor_sync(0xffffffffu, g0, 16);
    float g5 = __shfl_xor_sync(0xffffffffu, g1, 16);
    float g6 = __shfl_xor_sync(0xffffffffu, g2, 16);
    float g7 = __shfl_xor_sync(0xffffffffu, g3, 16);
    float gg[8] = {g0, g1, g2, g3, g4, g5, g6, g7};

    const ulonglong2 vv = *reinterpret_cast<const ulonglong2*>(&vf);
#pragma unroll
    for (int i = 0; i < 8; i++) {
        u64 pp = pack2(gg[i], gg[i]);
        fma2(a0[i], vv.x, pp);
        fma2(a1[i], vv.y, pp);
    }
}

// Flash-decode partial with fused q/k RoPE + 7-stage cp.async KV ring + fused
// last-CTA split reduce. grid = (kSplit, NKV, B), block = 128 (4 warps).
__global__ void __launch_bounds__(128)
attn_partial(const float* __restrict__ ck, const float* __restrict__ cv,
             const float* __restrict__ cosv, const float* __restrict__ sinv) {
    __shared__ float4 kbuf[4][kNS][32];
    __shared__ float4 vbuf[4][kNS][32];

    const int split = blockIdx.x, g = blockIdx.y, b = blockIdx.z;
    const int w = threadIdx.x >> 5, lane = threadIdx.x & 31;
    const int hbase = lane >> 2;
    const float cscale = 0.08838834764831845f * 1.4426950408889634f;
    const int d0 = lane * 4;
    const int dp = d0 ^ 64;
    const float sg = (d0 < 64) ? -1.f : 1.f;

    const float4 c4 = *reinterpret_cast<const float4*>(cosv + d0);
    const float4 s4 = *reinterpret_cast<const float4*>(sinv + d0);

    // RoPE + scale per-head q, then repack into head-pair layout qp[d][j].
    float4 qv[8];
#pragma unroll
    for (int i = 0; i < 8; i++) {
        int h = hbase ^ i;
        const float* qr = g_q + ((size_t)b * kNH + g * 8 + h) * kHD;
        float4 xo = *reinterpret_cast<const float4*>(qr + d0);
        float4 xp = *reinterpret_cast<const float4*>(qr + dp);
        qv[i] = make_float4((xo.x * c4.x + sg * xp.x * s4.x) * cscale,
                            (xo.y * c4.y + sg * xp.y * s4.y) * cscale,
                            (xo.z * c4.z + sg * xp.z * s4.z) * cscale,
                            (xo.w * c4.w + sg * xp.w * s4.w) * cscale);
    }
    u64 qp[4][4];
#pragma unroll
    for (int j = 0; j < 4; j++) {
        qp[0][j] = pack2(qv[2 * j].x, qv[2 * j + 1].x);
        qp[1][j] = pack2(qv[2 * j].y, qv[2 * j + 1].y);
        qp[2][j] = pack2(qv[2 * j].z, qv[2 * j + 1].z);
        qp[3][j] = pack2(qv[2 * j].w, qv[2 * j + 1].w);
    }

    float l = 0.f;
    u64 a0[8], a1[8];
#pragma unroll
    for (int i = 0; i < 8; i++) { a0[i] = 0ull; a1[i] = 0ull; }

    const int lo = split * kChunk;
    const int hi = min(lo + kChunk, kStart);
    const size_t stride = (size_t)kNKV * kHD;
    const size_t base = ((size_t)b * kMax * kNKV + g) * kHD + d0;

    const unsigned sk = (unsigned)__cvta_generic_to_shared(&kbuf[w][0][lane]);
    const unsigned sv = (unsigned)__cvta_generic_to_shared(&vbuf[w][0][lane]);
    const int t0 = lo + w;

#pragma unroll
    for (int s = 0; s < kNS - 1; s++) {
        int tt = t0 + 4 * s;
        if (tt < hi) {
            const size_t off = base + (size_t)tt * stride;
            cpasync16(sk + s * 512, ck + off);
            cpasync16(sv + s * 512, cv + off);
        }
        cpcommit();
    }

    int rd = 0;
#pragma unroll 2
    for (int t = t0; t < hi; t += 4) {
        cpwaitg<kNS - 2>();
        float4 kf = kbuf[w][rd][lane];
        float4 vf = vbuf[w][rd][lane];
        int wr = (rd == 0) ? (kNS - 1) : (rd - 1);
        int tn = t + (kNS - 1) * 4;
        if (tn < hi) {
            const size_t off = base + (size_t)tn * stride;
            cpasync16(sk + wr * 512, ck + off);
            cpasync16(sv + wr * 512, cv + off);
        }
        cpcommit();
        rd = (rd == kNS - 1) ? 0 : (rd + 1);

        attn_step(kf, vf, qp, l, a0, a1);
    }

    if (split == kSplit - 1 && w == 3) {          // t = 8191: fresh k/v, RoPE k inline
        const float* kr = g_k + ((size_t)b * kNKV + g) * kHD;
        float4 xo = *reinterpret_cast<const float4*>(kr + d0);
        float4 xp = *reinterpret_cast<const float4*>(kr + dp);
        float4 kf = make_float4(xo.x * c4.x + sg * xp.x * s4.x,
                                xo.y * c4.y + sg * xp.y * s4.y,
                                xo.z * c4.z + sg * xp.z * s4.z,
                                xo.w * c4.w + sg * xp.w * s4.w);
        float4 vf = *reinterpret_cast<const float4*>(
            g_v + ((size_t)b * kNKV + g) * kHD + d0);
        attn_step(kf, vf, qp, l, a0, a1);
    }

    __shared__ float4 sacc[4][8][32];
    __shared__ float  sl[4][8];
#pragma unroll
    for (int i = 0; i < 8; i++) {                  // slot i -> head hbase^i
        float x, y, z, ww_;
        unpack2(a0[i], x, y);
        unpack2(a1[i], z, ww_);
        sacc[w][hbase ^ i][lane] = make_float4(x, y, z, ww_);
    }
    if ((lane & 3) == 0) sl[w][hbase] = l;
    __syncthreads();

    const int bg = b * kNKV + g;
    const float* sa = reinterpret_cast<const float*>(sacc);
    float* outp = g_pacc + ((size_t)bg * kSplit + split) * (8 * kHD);
    for (int i = threadIdx.x; i < 8 * kHD; i += 128)
        outp[i] = sa[i] + sa[1024 + i] + sa[2048 + i] + sa[3072 + i];
    if (threadIdx.x < 8) {
        int h = threadIdx.x;
        g_pl[(bg * kSplit + split) * 8 + h] =
            sl[0][h] + sl[1][h] + sl[2][h] + sl[3][h];
    }

    // ---- fused split reduce: last CTA of this (b,g) combines all partials ----
    __shared__ int s_last;
    __threadfence();                               // partials visible device-wide
    __syncthreads();                               // all threads' stores issued
    if (threadIdx.x == 0)
        s_last = (atomicAdd(&g_cnt[bg], 1) == kSplit - 1) ? 1 : 0;
    __syncthreads();
    if (!s_last) return;

    __threadfence();                               // acquire other CTAs' partials
    __shared__ float invL[8];
    if (threadIdx.x < 8) {
        float L = 0.f;
#pragma unroll
        for (int s = 0; s < kSplit; s++)
            L += g_pl[(bg * kSplit + s) * 8 + threadIdx.x];
        invL[threadIdx.x] = 1.f / L;
    }
    __syncthreads();
    const float* pb = g_pacc + (size_t)bg * kSplit * (8 * kHD);
    for (int i = threadIdx.x; i < 8 * kHD; i += 128) {
        float v = 0.f;
#pragma unroll
        for (int s = 0; s < kSplit; s++) v += pb[s * (8 * kHD) + i];
        int h = i >> 7, d = i & 127;
        g_attn[(size_t)b * kHid + (g * 8 + h) * kHD + d] = v * invL[h];
    }
}

extern "C" void kernel_launch(void* const* d_in, const int* in_sizes, int n_in,
                              void* d_out, int out_size) {
    const float* x    = (const float*)d_in[0];
    const float* cosv = (const float*)d_in[1];
    const float* sinv = (const float*)d_in[2];
    const float* wq   = (const float*)d_in[3];
    const float* bq   = (const float*)d_in[4];
    const float* wk   = (const float*)d_in[5];
    const float* bk   = (const float*)d_in[6];
    const float* wv   = (const float*)d_in[7];
    const float* bv   = (const float*)d_in[8];
    const float* wo   = (const float*)d_in[9];
    const float* ck   = (const float*)d_in[10];
    const float* cv   = (const float*)d_in[11];
    float* out = (float*)d_out;

    float* pattn;
    cudaGetSymbolAddress((void**)&pattn, g_attn);

    cudaFuncSetAttribute(qkv_kernel, cudaFuncAttributeMaxDynamicSharedMemorySize, kGemmSmem);
    cudaFuncSetAttribute(out_gemm_kernel, cudaFuncAttributeMaxDynamicSharedMemorySize, kGemmSmem);

    qkv_kernel<<<dim3(80, kB / 8), 256, kGemmSmem>>>(x, wq, bq, wk, bk, wv, bv);
    attn_partial<<<dim3(kSplit, kNKV, kB), 128>>>(ck, cv, cosv, sinv);
    out_gemm_kernel<<<dim3(kHid / 32, kB / 8), 256, kGemmSmem>>>(pattn, wo, out);
}

// round 16
// speedup vs baseline: 1.0468x; 1.0468x over previous
#include <cuda_runtime.h>

namespace {
constexpr int kB    = 64;
constexpr int kNH   = 16;
constexpr int kNKV  = 2;
constexpr int kHD   = 128;
constexpr int kMax  = 8192;
constexpr int kHid  = 2048;
constexpr int kStart= 8191;
constexpr int kSplit= 23;
constexpr int kChunk= 357;   // 23*357 = 8211 >= 8191
constexpr int kNS   = 7;     // attn cp.async ring stages per warp
constexpr int kGemmSmem = 64 * 1024;   // xs: 8 batches x 2048 floats
}

typedef unsigned long long u64;

__device__ __align__(16) float g_q[kB * kNH * kHD];     // pre-RoPE q
__device__ __align__(16) float g_k[kB * kNKV * kHD];    // pre-RoPE k
__device__ __align__(16) float g_v[kB * kNKV * kHD];
__device__ __align__(16) float g_attn[kB * kHid];
__device__ __align__(16) float g_pacc[kB * kNKV * kSplit * 8 * kHD];
__device__ __align__(16) float g_pl[kB * kNKV * kSplit * 8];
__device__ int g_cnt[kB * kNKV];                        // split-arrival counters

__device__ __forceinline__ u64 pack2(float lo, float hi) {
    u64 r; asm("mov.b64 %0,{%1,%2};" : "=l"(r) : "f"(lo), "f"(hi)); return r;
}
__device__ __forceinline__ void unpack2(u64 v, float& lo, float& hi) {
    asm("mov.b64 {%0,%1},%2;" : "=f"(lo), "=f"(hi) : "l"(v));
}
__device__ __forceinline__ void fma2(u64& d, u64 a, u64 b) {
    asm("fma.rn.f32x2 %0,%1,%2,%0;" : "+l"(d) : "l"(a), "l"(b));
}
__device__ __forceinline__ u64 mul2(u64 a, u64 b) {
    u64 r; asm("mul.rn.f32x2 %0,%1,%2;" : "=l"(r) : "l"(a), "l"(b)); return r;
}
__device__ __forceinline__ u64 add2(u64 a, u64 b) {
    u64 r; asm("add.rn.f32x2 %0,%1,%2;" : "=l"(r) : "l"(a), "l"(b)); return r;
}
__device__ __forceinline__ u64 shfl64x(u64 v, int m) {
    return __shfl_xor_sync(0xffffffffu, v, m);
}
__device__ __forceinline__ void cpasync16(unsigned saddr, const void* g) {
    asm volatile("cp.async.cg.shared.global [%0], [%1], 16;" :: "r"(saddr), "l"(g));
}
__device__ __forceinline__ void cpcommit() {
    asm volatile("cp.async.commit_group;" ::: "memory");
}
template <int N>
__device__ __forceinline__ void cpwaitg() {
    asm volatile("cp.async.wait_group %0;" :: "n"(N) : "memory");
}

// ---------------------------------------------------------------------------
// GEMM (R8 measured-best): out[b][o] = sum_k X[b][k] * W[o][k] + bias[o].
// block = 256 (8 warps). CTA tile: 32 outputs x 8 batches; warp: 4 outputs.
// X staged once in 64KB smem (cp.async); barrier-free ki loop with depth-1
// register prefetch of the weight slice. Batch index permuted (lane>>2)^ih
// in the accumulator for the XOR-fold epilogue.
__device__ __forceinline__ void gemm_body(const float* __restrict__ X,
                                          const float* __restrict__ W,
                                          const float* __restrict__ bias,
                                          float* __restrict__ out,
                                          int N, int b0, int o0) {
    extern __shared__ float4 xs[];           // [8][512] float4
    const unsigned xs_s = (unsigned)__cvta_generic_to_shared(xs);

    const int tid  = threadIdx.x;
    const int w    = tid >> 5;
    const int lane = tid & 31;
    const int ob   = o0 + w * 4;
    const int hb   = lane >> 2;

    // Stage all of X for this batch group: 4096 16B chunks, 16 per thread.
#pragma unroll
    for (int j = 0; j < 16; j++) {
        int c = tid + j * 256;               // c>>9 = batch, c&511 = float4 idx
        cpasync16(xs_s + c * 16,
                  X + (size_t)(b0 + (c >> 9)) * kHid + (c & 511) * 4);
    }
    cpcommit();

    // Preload weights for ki=0 while the X copy is in flight.
    const float* wrow0 = W + (size_t)ob * kHid + lane * 4;
    ulonglong2 wv[4];
#pragma unroll
    for (int oo = 0; oo < 4; oo++)
        wv[oo] = *reinterpret_cast<const ulonglong2*>(wrow0 + (size_t)oo * kHid);

    u64 acc[8][4];
#pragma unroll
    for (int i = 0; i < 8; i++)
#pragma unroll
        for (int j = 0; j < 4; j++) acc[i][j] = 0ull;

    cpwaitg<0>();
    __syncthreads();                          // xs ready; no barriers after this

#pragma unroll 1
    for (int ki = 0; ki < 16; ki++) {
        ulonglong2 wn[4];
        if (ki < 15) {                        // depth-1 weight prefetch
#pragma unroll
            for (int oo = 0; oo < 4; oo++)
                wn[oo] = *reinterpret_cast<const ulonglong2*>(
                    wrow0 + (size_t)oo * kHid + (ki + 1) * 128);
        }
        const int kk = ki * 32 + lane;        // float4 index within a batch row
#pragma unroll
        for (int ih = 0; ih < 8; ih++) {
            ulonglong2 xv = *reinterpret_cast<const ulonglong2*>(
                xs + ((hb ^ ih) << 9) + kk);
#pragma unroll
            for (int oo = 0; oo < 4; oo++) {
                fma2(acc[ih][oo], xv.x, wv[oo].x);
                fma2(acc[ih][oo], xv.y, wv[oo].y);
            }
        }
#pragma unroll
        for (int oo = 0; oo < 4; oo++) wv[oo] = wn[oo];
    }

    // Epilogue: slot ih on lane l holds batch (l>>2)^ih. XOR-fold per oo.
    float s[4][8];
#pragma unroll
    for (int ih = 0; ih < 8; ih++)
#pragma unroll
        for (int oo = 0; oo < 4; oo++) {
            float lo, hi; unpack2(acc[ih][oo], lo, hi);
            s[oo][ih] = lo + hi;
        }
#pragma unroll
    for (int oo = 0; oo < 4; oo++) {
#pragma unroll
        for (int i = 0; i < 4; i++) s[oo][i] += __shfl_xor_sync(0xffffffffu, s[oo][i ^ 4], 16);
#pragma unroll
        for (int i = 0; i < 2; i++) s[oo][i] += __shfl_xor_sync(0xffffffffu, s[oo][i ^ 2], 8);
        s[oo][0] += __shfl_xor_sync(0xffffffffu, s[oo][1], 4);
        s[oo][0] += __shfl_xor_sync(0xffffffffu, s[oo][0], 2);
        s[oo][0] += __shfl_xor_sync(0xffffffffu, s[oo][0], 1);
    }
    // lane l holds totals of batch hb for all oo; it writes oo = l&3.
    float r01 = (lane & 1) ? s[1][0] : s[0][0];
    float r23 = (lane & 1) ? s[3][0] : s[2][0];
    float r   = (lane & 2) ? r23 : r01;
    int oo = lane & 3;
    float bv = bias ? bias[ob + oo] : 0.f;
    out[(size_t)(b0 + hb) * N + ob + oo] = r + bv;
}

// Fused QKV: blocks 0..63 -> q (N=2048), 64..71 -> k, 72..79 -> v (N=256).
// Block (0,0) also resets the split-arrival counters for attn's fused reduce.
__global__ void __launch_bounds__(256, 2)
qkv_kernel(const float* __restrict__ X,
           const float* __restrict__ wq, const float* __restrict__ bq,
           const float* __restrict__ wk, const float* __restrict__ bk,
           const float* __restrict__ wv, const float* __restrict__ bv) {
    const int bx = blockIdx.x;
    const int b0 = blockIdx.y * 8;
    if (bx == 0 && blockIdx.y == 0 && threadIdx.x < kB * kNKV)
        g_cnt[threadIdx.x] = 0;
    if (bx < 64)       gemm_body(X, wq, bq, g_q, kHid, b0, bx * 32);
    else if (bx < 72)  gemm_body(X, wk, bk, g_k, 256, b0, (bx - 64) * 32);
    else               gemm_body(X, wv, bv, g_v, 256, b0, (bx - 72) * 32);
}

__global__ void __launch_bounds__(256, 2)
out_gemm_kernel(const float* __restrict__ X, const float* __restrict__ W,
                float* __restrict__ out) {
    gemm_body(X, W, nullptr, out, kHid, blockIdx.y * 8, blockIdx.x * 32);
}

// ---------------------------------------------------------------------------
// One timestep, packed head-pair scores.
// Lane ell owns dims [4*ell, 4*ell+4); slot i <-> head (ell>>2)^i.
// qp[d][j] = (q_{slot 2j, dim d}, q_{slot 2j+1, dim d}), pre-scaled.
__device__ __forceinline__ void attn_step(const float4 kf, const float4 vf,
                                          const u64 (* __restrict__ qp)[4],
                                          float& l,
                                          u64* __restrict__ a0,
                                          u64* __restrict__ a1) {
    const u64 kd0 = pack2(kf.x, kf.x);
    const u64 kd1 = pack2(kf.y, kf.y);
    const u64 kd2 = pack2(kf.z, kf.z);
    const u64 kd3 = pack2(kf.w, kf.w);

    u64 p[4];
#pragma unroll
    for (int j = 0; j < 4; j++) {
        p[j] = mul2(kd0, qp[0][j]);
        fma2(p[j], kd1, qp[1][j]);
        fma2(p[j], kd2, qp[2][j]);
        fma2(p[j], kd3, qp[3][j]);
    }
    // Packed XOR fold: pair j holds slots (2j, 2j+1).
    p[0] = add2(p[0], shfl64x(p[2], 16));     // level 16: partner pair j^2
    p[1] = add2(p[1], shfl64x(p[3], 16));
    p[0] = add2(p[0], shfl64x(p[1], 8));      // level 8:  partner pair j^1
    u64 t = shfl64x(p[0], 4);                 // level 4:  cross within pair
    float s0, s1_, t0_, t1;
    unpack2(p[0], s0, s1_);
    unpack2(t, t0_, t1);
    float s = s0 + t1;
    s += __shfl_xor_sync(0xffffffffu, s, 2);
    s += __shfl_xor_sync(0xffffffffu, s, 1);

    float pe;                                  // q pre-scaled by scale*log2(e)
    asm("ex2.approx.f32 %0, %1;" : "=f"(pe) : "f"(s));
    l += pe;                                   // denominator of head lane>>2

    float g0 = pe;
    float g1 = __shfl_xor_sync(0xffffffffu, g0, 4);
    float g2 = __shfl_xor_sync(0xffffffffu, g0, 8);
    float g3 = __shfl_xor_sync(0xffffffffu, g1, 8);
    float g4 = __shfl_xor_sync(0xffffffffu, g0, 16);
    float g5 = __shfl_xor_sync(0xffffffffu, g1, 16);
    float g6 = __shfl_xor_sync(0xffffffffu, g2, 16);
    float g7 = __shfl_xor_sync(0xffffffffu, g3, 16);
    float gg[8] = {g0, g1, g2, g3, g4, g5, g6, g7};

    const ulonglong2 vv = *reinterpret_cast<const ulonglong2*>(&vf);
#pragma unroll
    for (int i = 0; i < 8; i++) {
        u64 pp = pack2(gg[i], gg[i]);
        fma2(a0[i], vv.x, pp);
        fma2(a1[i], vv.y, pp);
    }
}

// Flash-decode partial with fused q/k RoPE + 7-stage cp.async KV ring + fused
// last-CTA split reduce. grid = (kSplit, NKV, B), block = 128 (4 warps).
__global__ void __launch_bounds__(128)
attn_partial(const float* __restrict__ ck, const float* __restrict__ cv,
             const float* __restrict__ cosv, const float* __restrict__ sinv) {
    __shared__ float4 kbuf[4][kNS][32];
    __shared__ float4 vbuf[4][kNS][32];

    const int split = blockIdx.x, g = blockIdx.y, b = blockIdx.z;
    const int w = threadIdx.x >> 5, lane = threadIdx.x & 31;
    const int hbase = lane >> 2;
    const float cscale = 0.08838834764831845f * 1.4426950408889634f;
    const int d0 = lane * 4;
    const int dp = d0 ^ 64;
    const float sg = (d0 < 64) ? -1.f : 1.f;

    const float4 c4 = *reinterpret_cast<const float4*>(cosv + d0);
    const float4 s4 = *reinterpret_cast<const float4*>(sinv + d0);

    // RoPE + scale per-head q, then repack into head-pair layout qp[d][j].
    float4 qv[8];
#pragma unroll
    for (int i = 0; i < 8; i++) {
        int h = hbase ^ i;
        const float* qr = g_q + ((size_t)b * kNH + g * 8 + h) * kHD;
        float4 xo = *reinterpret_cast<const float4*>(qr + d0);
        float4 xp = *reinterpret_cast<const float4*>(qr + dp);
        qv[i] = make_float4((xo.x * c4.x + sg * xp.x * s4.x) * cscale,
                            (xo.y * c4.y + sg * xp.y * s4.y) * cscale,
                            (xo.z * c4.z + sg * xp.z * s4.z) * cscale,
                            (xo.w * c4.w + sg * xp.w * s4.w) * cscale);
    }
    u64 qp[4][4];
#pragma unroll
    for (int j = 0; j < 4; j++) {
        qp[0][j] = pack2(qv[2 * j].x, qv[2 * j + 1].x);
        qp[1][j] = pack2(qv[2 * j].y, qv[2 * j + 1].y);
        qp[2][j] = pack2(qv[2 * j].z, qv[2 * j + 1].z);
        qp[3][j] = pack2(qv[2 * j].w, qv[2 * j + 1].w);
    }

    float l = 0.f;
    u64 a0[8], a1[8];
#pragma unroll
    for (int i = 0; i < 8; i++) { a0[i] = 0ull; a1[i] = 0ull; }

    const int lo = split * kChunk;
    const int hi = min(lo + kChunk, kStart);
    const size_t stride = (size_t)kNKV * kHD;
    const size_t base = ((size_t)b * kMax * kNKV + g) * kHD + d0;

    const unsigned sk = (unsigned)__cvta_generic_to_shared(&kbuf[w][0][lane]);
    const unsigned sv = (unsigned)__cvta_generic_to_shared(&vbuf[w][0][lane]);
    const int t0 = lo + w;

#pragma unroll
    for (int s = 0; s < kNS - 1; s++) {
        int tt = t0 + 4 * s;
        if (tt < hi) {
            const size_t off = base + (size_t)tt * stride;
            cpasync16(sk + s * 512, ck + off);
            cpasync16(sv + s * 512, cv + off);
        }
        cpcommit();
    }

    int rd = 0;
#pragma unroll 2
    for (int t = t0; t < hi; t += 4) {
        cpwaitg<kNS - 2>();
        float4 kf = kbuf[w][rd][lane];
        float4 vf = vbuf[w][rd][lane];
        int wr = (rd == 0) ? (kNS - 1) : (rd - 1);
        int tn = t + (kNS - 1) * 4;
        if (tn < hi) {
            const size_t off = base + (size_t)tn * stride;
            cpasync16(sk + wr * 512, ck + off);
            cpasync16(sv + wr * 512, cv + off);
        }
        cpcommit();
        rd = (rd == kNS - 1) ? 0 : (rd + 1);

        attn_step(kf, vf, qp, l, a0, a1);
    }

    if (split == kSplit - 1 && w == 3) {          // t = 8191: fresh k/v, RoPE k inline
        const float* kr = g_k + ((size_t)b * kNKV + g) * kHD;
        float4 xo = *reinterpret_cast<const float4*>(kr + d0);
        float4 xp = *reinterpret_cast<const float4*>(kr + dp);
        float4 kf = make_float4(xo.x * c4.x + sg * xp.x * s4.x,
                                xo.y * c4.y + sg * xp.y * s4.y,
                                xo.z * c4.z + sg * xp.z * s4.z,
                                xo.w * c4.w + sg * xp.w * s4.w);
        float4 vf = *reinterpret_cast<const float4*>(
            g_v + ((size_t)b * kNKV + g) * kHD + d0);
        attn_step(kf, vf, qp, l, a0, a1);
    }

    __shared__ float4 sacc[4][8][32];
    __shared__ float  sl[4][8];
#pragma unroll
    for (int i = 0; i < 8; i++) {                  // slot i -> head hbase^i
        float x, y, z, ww_;
        unpack2(a0[i], x, y);
        unpack2(a1[i], z, ww_);
        sacc[w][hbase ^ i][lane] = make_float4(x, y, z, ww_);
    }
    if ((lane & 3) == 0) sl[w][hbase] = l;
    __syncthreads();

    const int bg = b * kNKV + g;
    const float* sa = reinterpret_cast<const float*>(sacc);
    float* outp = g_pacc + ((size_t)bg * kSplit + split) * (8 * kHD);
    for (int i = threadIdx.x; i < 8 * kHD; i += 128)
        outp[i] = sa[i] + sa[1024 + i] + sa[2048 + i] + sa[3072 + i];
    if (threadIdx.x < 8) {
        int h = threadIdx.x;
        g_pl[(bg * kSplit + split) * 8 + h] =
            sl[0][h] + sl[1][h] + sl[2][h] + sl[3][h];
    }

    // ---- fused split reduce: last CTA of this (b,g) combines all partials ----
    __shared__ int s_last;
    __threadfence();                               // partials visible device-wide
    __syncthreads();                               // all threads' stores issued
    if (threadIdx.x == 0)
        s_last = (atomicAdd(&g_cnt[bg], 1) == kSplit - 1) ? 1 : 0;
    __syncthreads();
    if (!s_last) return;

    __threadfence();                               // acquire other CTAs' partials
    __shared__ float invL[8];
    if (threadIdx.x < 8) {
        float L = 0.f;
#pragma unroll
        for (int s = 0; s < kSplit; s++)
            L += g_pl[(bg * kSplit + s) * 8 + threadIdx.x];
        invL[threadIdx.x] = 1.f / L;
    }
    __syncthreads();
    const float* pb = g_pacc + (size_t)bg * kSplit * (8 * kHD);
    for (int i = threadIdx.x; i < 8 * kHD; i += 128) {
        float v = 0.f;
#pragma unroll
        for (int s = 0; s < kSplit; s++) v += pb[s * (8 * kHD) + i];
        int h = i >> 7, d = i & 127;
        g_attn[(size_t)b * kHid + (g * 8 + h) * kHD + d] = v * invL[h];
    }
}

extern "C" void kernel_launch(void* const* d_in, const int* in_sizes, int n_in,
                              void* d_out, int out_size) {
    const float* x    = (const float*)d_in[0];
    const float* cosv = (const float*)d_in[1];
    const float* sinv = (const float*)d_in[2];
    const float* wq   = (const float*)d_in[3];
    const float* bq   = (const float*)d_in[4];
    const float* wk   = (const float*)d_in[5];
    const float* bk   = (const float*)d_in[6];
    const float* wv   = (const float*)d_in[7];
    const float* bv   = (const float*)d_in[8];
    const float* wo   = (const float*)d_in[9];
    const float* ck   = (const float*)d_in[10];
    const float* cv   = (const float*)d_in[11];
    float* out = (float*)d_out;

    float* pattn;
    cudaGetSymbolAddress((void**)&pattn, g_attn);

    cudaFuncSetAttribute(qkv_kernel, cudaFuncAttributeMaxDynamicSharedMemorySize, kGemmSmem);
    cudaFuncSetAttribute(out_gemm_kernel, cudaFuncAttributeMaxDynamicSharedMemorySize, kGemmSmem);

    qkv_kernel<<<dim3(80, kB / 8), 256, kGemmSmem>>>(x, wq, bq, wk, bk, wv, bv);
    attn_partial<<<dim3(kSplit, kNKV, kB), 128>>>(ck, cv, cosv, sinv);
    out_gemm_kernel<<<dim3(kHid / 32, kB / 8), 256, kGemmSmem>>>(pattn, wo, out);
}